// round 2
// baseline (speedup 1.0000x reference)
#include <cuda_runtime.h>
#include <cstdint>

// GCNStage4_ReduceSum: out[t] += msg[e] for t = edge_index[1][e]
// msg: [NUM_EDGES, 32] f32; edge_index: [2, NUM_EDGES] (harness materializes as int32);
// out: [num_nodes, 32] f32
//
// Strategy: zero output, then 8 lanes per edge doing red.global.add.v4.f32
// (no-return vector reduction, resolves at L2 — output fits in L2 easily).

#define FEAT 32

__global__ void zero_out_kernel(float4* __restrict__ out, int n4) {
    int i = blockIdx.x * blockDim.x + threadIdx.x;
    if (i < n4) out[i] = make_float4(0.f, 0.f, 0.f, 0.f);
}

__global__ void scatter_add_kernel(const float4* __restrict__ msg4,
                                   const int* __restrict__ tgt,
                                   float* __restrict__ out,
                                   int num_edges) {
    int tid = blockIdx.x * blockDim.x + threadIdx.x;
    int e   = tid >> 3;      // edge id
    int sub = tid & 7;       // which float4 of the 32-float row
    if (e >= num_edges) return;

    int t = tgt[e];                             // L1-broadcast across the 8 lanes
    float4 v = msg4[(size_t)e * 8 + sub];       // coalesced: 8 lanes = 128B row

    float* dst = out + (size_t)t * FEAT + sub * 4;
    asm volatile("red.global.add.v4.f32 [%0], {%1, %2, %3, %4};"
                 :: "l"(dst), "f"(v.x), "f"(v.y), "f"(v.z), "f"(v.w)
                 : "memory");
}

extern "C" void kernel_launch(void* const* d_in, const int* in_sizes, int n_in,
                              void* d_out, int out_size) {
    const float4* msg4 = (const float4*)d_in[0];
    const int*    ei   = (const int*)d_in[1];   // harness stores indices as int32
    float*        out  = (float*)d_out;

    int num_edges = in_sizes[0] / FEAT;          // 1,600,000
    const int* tgt = ei + num_edges;             // row 1 of edge_index

    // 1) zero the output (poisoned to 0xAA by harness)
    int n4 = out_size / 4;
    zero_out_kernel<<<(n4 + 255) / 256, 256>>>((float4*)d_out, n4);

    // 2) scatter-add, 8 lanes per edge
    long long total_threads = (long long)num_edges * 8;
    int threads = 256;
    int blocks = (int)((total_threads + threads - 1) / threads);
    scatter_add_kernel<<<blocks, threads>>>(msg4, tgt, out, num_edges);
}

// round 3
// speedup vs baseline: 1.0975x; 1.0975x over previous
#include <cuda_runtime.h>
#include <cstdint>

// GCNStage4_ReduceSum: out[t] += msg[e] for t = edge_index[1][e]
// msg: [NUM_EDGES, 32] f32; edge_index: [2, NUM_EDGES] int32 (harness); out: [num_nodes, 32] f32
//
// R3: MLP-optimized. Each thread processes UNROLL=4 edge-fragments (8 lanes per
// edge), issuing all loads before any reduction -> MLP~8 in flight per thread.
// red.global.add.v4.f32 is no-return (fire-and-forget, resolves in L2).
// Output zeroed via cudaMemsetAsync (graph-capturable).

#define FEAT 32
#define UNROLL 4

__global__ void __launch_bounds__(256) scatter_add_kernel(
        const float4* __restrict__ msg4,
        const int* __restrict__ tgt,
        float* __restrict__ out,
        int num_frags)   // num_edges * 8
{
    int tid = blockIdx.x * blockDim.x + threadIdx.x;
    int stride = gridDim.x * blockDim.x;

    int   t[UNROLL];
    float4 v[UNROLL];
    int   id[UNROLL];

    // Phase 1: issue all loads (front-batched -> high MLP)
    #pragma unroll
    for (int u = 0; u < UNROLL; u++) {
        id[u] = tid + u * stride;
        if (id[u] < num_frags) {
            int e   = id[u] >> 3;
            int sub = id[u] & 7;
            t[u] = tgt[e];                                   // broadcast across 8 lanes
            v[u] = __ldcs(&msg4[(size_t)e * 8 + sub]);       // streaming: no reuse
        }
    }

    // Phase 2: fire-and-forget vector reductions
    #pragma unroll
    for (int u = 0; u < UNROLL; u++) {
        if (id[u] < num_frags) {
            int sub = id[u] & 7;
            float* dst = out + (size_t)t[u] * FEAT + sub * 4;
            asm volatile("red.global.add.v4.f32 [%0], {%1, %2, %3, %4};"
                         :: "l"(dst), "f"(v[u].x), "f"(v[u].y), "f"(v[u].z), "f"(v[u].w)
                         : "memory");
        }
    }
}

extern "C" void kernel_launch(void* const* d_in, const int* in_sizes, int n_in,
                              void* d_out, int out_size) {
    const float4* msg4 = (const float4*)d_in[0];
    const int*    ei   = (const int*)d_in[1];   // int32 indices
    float*        out  = (float*)d_out;

    int num_edges = in_sizes[0] / FEAT;          // 1,600,000
    const int* tgt = ei + num_edges;             // row 1 of edge_index

    // 1) zero the output (poisoned to 0xAA by harness); memset is capturable
    cudaMemsetAsync(d_out, 0, (size_t)out_size * sizeof(float));

    // 2) scatter-add: 8 lanes per edge, 4 fragments per thread
    int num_frags = num_edges * 8;                       // 12.8M
    int threads = 256;
    long long total_threads = (num_frags + UNROLL - 1) / UNROLL;
    int blocks = (int)((total_threads + threads - 1) / threads);
    scatter_add_kernel<<<blocks, threads>>>(msg4, tgt, out, num_frags);
}